// round 4
// baseline (speedup 1.0000x reference)
#include <cuda_runtime.h>
#include <stdint.h>

#define N_NODES 50000
#define N_EDGES 800000
#define IN_CH 384
#define HID 128

// ---------------- scratch (no allocation allowed) ----------------
__device__ __align__(256) float g_buf[N_NODES * HID];  // single 25.6MB scratch
__device__ float g_deg[N_NODES];
__device__ float g_dinv[N_NODES];

// ---------------- degree / norm ----------------
__global__ void deg_init_kernel() {
    int i = blockIdx.x * blockDim.x + threadIdx.x;
    if (i < N_NODES) g_deg[i] = 1.0f;  // self loop
}

__global__ void deg_count_kernel(const int* __restrict__ dst) {
    int e = blockIdx.x * blockDim.x + threadIdx.x;
    if (e < N_EDGES) {
        unsigned d = (unsigned)dst[e];
        if (d < N_NODES) atomicAdd(&g_deg[d], 1.0f);
    }
}

__global__ void dinv_kernel() {
    int i = blockIdx.x * blockDim.x + threadIdx.x;
    if (i < N_NODES) g_dinv[i] = rsqrtf(g_deg[i]);
}

// ---------------- GEMM: C[M,128] = A[M,K] @ W[K,128] (+bias) ----------------
// 128 threads/block, one output column per thread, 32 rows per block.
// K-tiled by 64 (8KB smem). In-place safe when A == C (block reads only its
// own 32 rows into smem; writes them only at the end).
template <int K, bool A_SCR, bool C_SCR, bool BIAS>
__global__ void gemm_kernel(const float* __restrict__ A_ext,
                            float* __restrict__ C_ext,
                            const float* __restrict__ W,
                            const float* __restrict__ bias) {
    const float* A = A_SCR ? (const float*)g_buf : A_ext;
    float* C = C_SCR ? g_buf : C_ext;

    __shared__ float xs[32][64];
    const int col = threadIdx.x;          // 0..127
    const int row0 = blockIdx.x * 32;
    const int nrows = (N_NODES - row0) < 32 ? (N_NODES - row0) : 32;

    float acc[32];
#pragma unroll
    for (int r = 0; r < 32; r++) acc[r] = 0.0f;

    for (int k0 = 0; k0 < K; k0 += 64) {
        // load 32x64 tile as float4 (all offsets 16B-aligned)
        for (int i = threadIdx.x; i < nrows * 16; i += 128) {
            const int r = i >> 4;
            const int q = i & 15;
            const float4 v = *reinterpret_cast<const float4*>(
                &A[(size_t)(row0 + r) * K + k0 + q * 4]);
            xs[r][q * 4 + 0] = v.x;
            xs[r][q * 4 + 1] = v.y;
            xs[r][q * 4 + 2] = v.z;
            xs[r][q * 4 + 3] = v.w;
        }
        __syncthreads();

#pragma unroll 2
        for (int kk = 0; kk < 64; kk++) {
            const float wv = W[(size_t)(k0 + kk) * HID + col];
#pragma unroll
            for (int r = 0; r < 32; r++) {
                acc[r] = fmaf(xs[r][kk], wv, acc[r]);
            }
        }
        __syncthreads();
    }

    for (int r = 0; r < nrows; r++) {
        float v = acc[r];
        if (BIAS) v += bias[col];
        C[(size_t)(row0 + r) * HID + col] = v;
    }
}

// ---------------- self-loop init: agg[i] = dinv[v]^2 * g_buf[i] -------------
__global__ void self_loop_init_kernel(float* __restrict__ agg) {
    int i = blockIdx.x * blockDim.x + threadIdx.x;
    if (i < N_NODES * HID) {
        const float dv = g_dinv[i >> 7];
        agg[i] = dv * dv * g_buf[i];
    }
}

// ---------------- edge scatter: agg[dst] += dinv[s]*dinv[d]*g_buf[s] --------
// One warp per edge; lane handles channels lane, lane+32, lane+64, lane+96.
__global__ void scatter_kernel(const int* __restrict__ src,
                               const int* __restrict__ dst,
                               float* __restrict__ agg) {
    const int e = blockIdx.x * (blockDim.x >> 5) + (threadIdx.x >> 5);
    const int lane = threadIdx.x & 31;
    if (e >= N_EDGES) return;
    const unsigned s = (unsigned)src[e];
    const unsigned d = (unsigned)dst[e];
    if (s >= N_NODES || d >= N_NODES) return;
    const float norm = g_dinv[s] * g_dinv[d];

    const float* hrow = g_buf + (size_t)s * HID;
    float* arow = agg + (size_t)d * HID;
#pragma unroll
    for (int c = 0; c < 4; c++) {
        const int ch = lane + c * 32;
        atomicAdd(&arow[ch], norm * hrow[ch]);
    }
}

// ---------------- g_buf[i] = relu(agg[i] + b[c]) ----------------------------
__global__ void relu_bias_kernel(const float* __restrict__ agg,
                                 const float* __restrict__ b) {
    int i = blockIdx.x * blockDim.x + threadIdx.x;
    if (i < N_NODES * HID) {
        g_buf[i] = fmaxf(agg[i] + b[i & 127], 0.0f);
    }
}

extern "C" void kernel_launch(void* const* d_in, const int* in_sizes, int n_in,
                              void* d_out, int out_size) {
    const float* x   = (const float*)d_in[0];
    const int* ei    = (const int*)d_in[1];   // int64 marshaled as int32
    const float* W1  = (const float*)d_in[2];
    const float* b1  = (const float*)d_in[3];
    const float* W2  = (const float*)d_in[4];
    const float* b2  = (const float*)d_in[5];
    float* out       = (float*)d_out;

    const int* src = ei;            // edge_index[0]
    const int* dst = ei + N_EDGES;  // edge_index[1]

    const int ELEM = N_NODES * HID;
    const int eb = (ELEM + 255) / 256;
    const int nb = (N_NODES + 255) / 256;
    const int gemm_blocks = (N_NODES + 31) / 32;
    const int scatter_blocks = (N_EDGES + 7) / 8;  // 8 warps/block

    // degree + norm
    deg_init_kernel<<<nb, 256>>>();
    deg_count_kernel<<<(N_EDGES + 255) / 256, 256>>>(dst);
    dinv_kernel<<<nb, 256>>>();

    // layer 1: h1 = x@W1 (scratch); out = selfloop + scatter (agg1)
    gemm_kernel<IN_CH, false, true, false><<<gemm_blocks, 128>>>(x, nullptr, W1, nullptr);
    self_loop_init_kernel<<<eb, 256>>>(out);
    scatter_kernel<<<scatter_blocks, 256>>>(src, dst, out);

    // h2 = relu(agg1 + b1) (scratch)
    relu_bias_kernel<<<eb, 256>>>(out, b1);

    // layer 2 (reassociated): agg2 = A_hat*h2 (out); out = agg2@W2 + b2 (in-place)
    self_loop_init_kernel<<<eb, 256>>>(out);
    scatter_kernel<<<scatter_blocks, 256>>>(src, dst, out);
    gemm_kernel<HID, false, false, true><<<gemm_blocks, 128>>>(out, out, W2, b2);
}

// round 6
// speedup vs baseline: 1.5207x; 1.5207x over previous
#include <cuda_runtime.h>
#include <stdint.h>

#define N_NODES 50000
#define N_EDGES 800000
#define IN_CH 384
#define HID 128

// ---------------- scratch (no allocation allowed) ----------------
// NOTE: only ever referenced from DEVICE code (host-side symbol refs are UB,
// and cudaGetSymbolAddress is forbidden in the capture path).
__device__ __align__(256) float g_buf[N_NODES * HID];  // 25.6MB scratch
__device__ float g_deg[N_NODES];
__device__ float g_dinv[N_NODES];

// ---------------- degree / norm ----------------
__global__ void deg_init_kernel() {
    int i = blockIdx.x * blockDim.x + threadIdx.x;
    if (i < N_NODES) g_deg[i] = 1.0f;  // self loop
}

__global__ void deg_count_kernel(const int* __restrict__ dst) {
    int e = blockIdx.x * blockDim.x + threadIdx.x;
    if (e < N_EDGES) {
        unsigned d = (unsigned)dst[e];
        if (d < N_NODES) atomicAdd(&g_deg[d], 1.0f);
    }
}

__global__ void dinv_kernel() {
    int i = blockIdx.x * blockDim.x + threadIdx.x;
    if (i < N_NODES) g_dinv[i] = rsqrtf(g_deg[i]);
}

// ---------------- GEMM: C[M,128] = A[M,K] @ W[K,128] (+bias) ----------------
// Register-tiled: block tile 64x128, 128 threads (8 ty x 16 tx), each thread
// an 8x8 outer-product tile. K tiled by 16. A-tile stored transposed in smem.
// A_SCR/C_SCR select the g_buf scratch from DEVICE code. In-place safe (A==C).
template <int K, bool A_SCR, bool C_SCR, bool BIAS>
__global__ void __launch_bounds__(128)
gemm_rt_kernel(const float* __restrict__ A_ext, float* __restrict__ C_ext,
               const float* __restrict__ W, const float* __restrict__ bias) {
    const float* A = A_SCR ? (const float*)g_buf : A_ext;
    float* C = C_SCR ? g_buf : C_ext;

    constexpr int BK = 16;
    __shared__ float As[BK][68];    // [k][row], padded
    __shared__ float Bs[BK][132];   // [k][col], padded

    const int tid = threadIdx.x;
    const int tx = tid & 15;   // 0..15 -> col group (8 cols each)
    const int ty = tid >> 4;   // 0..7  -> row group (8 rows each)
    const int row0 = blockIdx.x * 64;

    float acc[8][8];
#pragma unroll
    for (int i = 0; i < 8; i++)
#pragma unroll
        for (int j = 0; j < 8; j++) acc[i][j] = 0.0f;

    for (int k0 = 0; k0 < K; k0 += BK) {
        // A tile: 64 rows x 16 k = 256 float4, 2 per thread, store transposed
#pragma unroll
        for (int i = 0; i < 2; i++) {
            const int f4 = i * 128 + tid;      // 0..255
            const int r = f4 >> 2;             // 0..63
            const int q = f4 & 3;              // 0..3
            const int grow = row0 + r;
            float4 v = make_float4(0.f, 0.f, 0.f, 0.f);
            if (grow < N_NODES)
                v = *reinterpret_cast<const float4*>(&A[(size_t)grow * K + k0 + q * 4]);
            As[q * 4 + 0][r] = v.x;
            As[q * 4 + 1][r] = v.y;
            As[q * 4 + 2][r] = v.z;
            As[q * 4 + 3][r] = v.w;
        }
        // B tile: 16 k x 128 cols = 512 float4, 4 per thread
#pragma unroll
        for (int i = 0; i < 4; i++) {
            const int f4 = i * 128 + tid;      // 0..511
            const int kk = f4 >> 5;            // 0..15
            const int c = (f4 & 31) * 4;
            const float4 v = *reinterpret_cast<const float4*>(&W[(size_t)(k0 + kk) * HID + c]);
            Bs[kk][c + 0] = v.x;
            Bs[kk][c + 1] = v.y;
            Bs[kk][c + 2] = v.z;
            Bs[kk][c + 3] = v.w;
        }
        __syncthreads();

#pragma unroll
        for (int kk = 0; kk < BK; kk++) {
            float a[8], b[8];
            *reinterpret_cast<float4*>(&a[0]) = *reinterpret_cast<const float4*>(&As[kk][ty * 8]);
            *reinterpret_cast<float4*>(&a[4]) = *reinterpret_cast<const float4*>(&As[kk][ty * 8 + 4]);
            *reinterpret_cast<float4*>(&b[0]) = *reinterpret_cast<const float4*>(&Bs[kk][tx * 8]);
            *reinterpret_cast<float4*>(&b[4]) = *reinterpret_cast<const float4*>(&Bs[kk][tx * 8 + 4]);
#pragma unroll
            for (int i = 0; i < 8; i++)
#pragma unroll
                for (int j = 0; j < 8; j++)
                    acc[i][j] = fmaf(a[i], b[j], acc[i][j]);
        }
        __syncthreads();
    }

    // epilogue
    float bv[8];
#pragma unroll
    for (int j = 0; j < 8; j++) bv[j] = BIAS ? bias[tx * 8 + j] : 0.0f;

#pragma unroll
    for (int i = 0; i < 8; i++) {
        const int grow = row0 + ty * 8 + i;
        if (grow < N_NODES) {
            float4 v0, v1;
            v0.x = acc[i][0] + bv[0]; v0.y = acc[i][1] + bv[1];
            v0.z = acc[i][2] + bv[2]; v0.w = acc[i][3] + bv[3];
            v1.x = acc[i][4] + bv[4]; v1.y = acc[i][5] + bv[5];
            v1.z = acc[i][6] + bv[6]; v1.w = acc[i][7] + bv[7];
            float* crow = &C[(size_t)grow * HID + tx * 8];
            *reinterpret_cast<float4*>(crow) = v0;
            *reinterpret_cast<float4*>(crow + 4) = v1;
        }
    }
}

// ---------------- self-loop init: agg[i] = dinv[v]^2 * g_buf[i] -------------
__global__ void self_loop_init_kernel(float* __restrict__ agg) {
    int i = blockIdx.x * blockDim.x + threadIdx.x;   // float4 index
    if (i < N_NODES * HID / 4) {
        const float dv = g_dinv[i >> 5];
        const float s = dv * dv;
        float4 v = reinterpret_cast<const float4*>(g_buf)[i];
        v.x *= s; v.y *= s; v.z *= s; v.w *= s;
        reinterpret_cast<float4*>(agg)[i] = v;
    }
}

// ------- fused: h = relu(agg + b); g_buf = h; agg = dinv^2 * h ---------------
__global__ void relu_selfloop_kernel(float* __restrict__ agg,
                                     const float* __restrict__ b) {
    int i = blockIdx.x * blockDim.x + threadIdx.x;   // float4 index
    if (i < N_NODES * HID / 4) {
        const float dv = g_dinv[i >> 5];
        const float s = dv * dv;
        const int c = (i & 31) * 4;
        float4 v = reinterpret_cast<const float4*>(agg)[i];
        v.x = fmaxf(v.x + b[c + 0], 0.0f);
        v.y = fmaxf(v.y + b[c + 1], 0.0f);
        v.z = fmaxf(v.z + b[c + 2], 0.0f);
        v.w = fmaxf(v.w + b[c + 3], 0.0f);
        reinterpret_cast<float4*>(g_buf)[i] = v;
        v.x *= s; v.y *= s; v.z *= s; v.w *= s;
        reinterpret_cast<float4*>(agg)[i] = v;
    }
}

// ---------------- edge scatter: agg[dst] += dinv[s]*dinv[d]*g_buf[s] --------
// One warp per edge; each lane does one 16B vector reduction (4 channels).
__global__ void scatter_kernel(const int* __restrict__ src,
                               const int* __restrict__ dst,
                               float* __restrict__ agg) {
    const int e = blockIdx.x * (blockDim.x >> 5) + (threadIdx.x >> 5);
    const int lane = threadIdx.x & 31;
    if (e >= N_EDGES) return;
    const unsigned s = (unsigned)src[e];
    const unsigned d = (unsigned)dst[e];
    if (s >= N_NODES || d >= N_NODES) return;
    const float norm = g_dinv[s] * g_dinv[d];

    const float4 v = reinterpret_cast<const float4*>(g_buf + (size_t)s * HID)[lane];
    float* p = agg + (size_t)d * HID + lane * 4;
    asm volatile("red.global.v4.f32.add [%0], {%1, %2, %3, %4};"
                 :: "l"(p), "f"(norm * v.x), "f"(norm * v.y),
                    "f"(norm * v.z), "f"(norm * v.w)
                 : "memory");
}

extern "C" void kernel_launch(void* const* d_in, const int* in_sizes, int n_in,
                              void* d_out, int out_size) {
    const float* x   = (const float*)d_in[0];
    const int* ei    = (const int*)d_in[1];   // int64 marshaled as int32
    const float* W1  = (const float*)d_in[2];
    const float* b1  = (const float*)d_in[3];
    const float* W2  = (const float*)d_in[4];
    const float* b2  = (const float*)d_in[5];
    float* out       = (float*)d_out;

    const int* src = ei;            // edge_index[0]
    const int* dst = ei + N_EDGES;  // edge_index[1]

    const int V4 = N_NODES * HID / 4;
    const int vb = (V4 + 255) / 256;
    const int nb = (N_NODES + 255) / 256;
    const int gemm_blocks = (N_NODES + 63) / 64;
    const int scatter_blocks = (N_EDGES + 7) / 8;  // 8 warps/block

    // degree + norm
    deg_init_kernel<<<nb, 256>>>();
    deg_count_kernel<<<(N_EDGES + 255) / 256, 256>>>(dst);
    dinv_kernel<<<nb, 256>>>();

    // layer 1: h1 = x@W1 (g_buf); out = dinv^2*h1 + scatter
    gemm_rt_kernel<IN_CH, false, true, false><<<gemm_blocks, 128>>>(x, nullptr, W1, nullptr);
    self_loop_init_kernel<<<vb, 256>>>(out);
    scatter_kernel<<<scatter_blocks, 256>>>(src, dst, out);

    // fused: g_buf = relu(out+b1) = h2 ; out = dinv^2*h2 (layer-2 self loop)
    relu_selfloop_kernel<<<vb, 256>>>(out, b1);

    // layer 2 (reassociated): out += scatter(h2); out = out@W2 + b2 (in-place)
    scatter_kernel<<<scatter_blocks, 256>>>(src, dst, out);
    gemm_rt_kernel<HID, false, false, true><<<gemm_blocks, 128>>>(out, out, W2, b2);
}

// round 7
// speedup vs baseline: 1.8201x; 1.1969x over previous
#include <cuda_runtime.h>
#include <stdint.h>

#define N_NODES 50000
#define N_EDGES 800000
#define IN_CH 384
#define HID 128

// ---------------- scratch (device-code-only references!) ----------------
__device__ __align__(256) float g_buf[N_NODES * HID];  // 25.6MB scratch
__device__ float g_dinv[N_NODES];
__device__ int g_degi[N_NODES];
__device__ int g_rowptr[N_NODES + 1];
__device__ int g_cursor[N_NODES];
__device__ int g_col[N_EDGES];

// ---------------- degree / norm / CSR ----------------
__global__ void degi_init_kernel() {
    int i = blockIdx.x * blockDim.x + threadIdx.x;
    if (i < N_NODES) g_degi[i] = 0;
}

__global__ void degi_count_kernel(const int* __restrict__ dst) {
    int e = blockIdx.x * blockDim.x + threadIdx.x;
    if (e < N_EDGES) {
        unsigned d = (unsigned)dst[e];
        if (d < N_NODES) atomicAdd(&g_degi[d], 1);
    }
}

__global__ void dinv_kernel() {
    int i = blockIdx.x * blockDim.x + threadIdx.x;
    if (i < N_NODES) g_dinv[i] = rsqrtf(1.0f + (float)g_degi[i]);
}

// single block, 1024 threads: exclusive scan of g_degi -> g_rowptr/g_cursor
__global__ void scan_kernel() {
    __shared__ int sums[1024];
    const int T = 1024;
    const int tid = threadIdx.x;
    const int per = (N_NODES + T - 1) / T;
    const int start = tid * per;
    const int end = (start + per < N_NODES) ? start + per : N_NODES;

    int s = 0;
    for (int i = start; i < end; i++) s += g_degi[i];
    sums[tid] = s;
    __syncthreads();
    for (int off = 1; off < T; off <<= 1) {
        int v = 0;
        if (tid >= off) v = sums[tid - off];
        __syncthreads();
        if (tid >= off) sums[tid] += v;
        __syncthreads();
    }
    int base = (tid == 0) ? 0 : sums[tid - 1];
    for (int i = start; i < end; i++) {
        g_rowptr[i] = base;
        g_cursor[i] = base;
        base += g_degi[i];
    }
    if (tid == T - 1) g_rowptr[N_NODES] = base;
}

__global__ void fill_kernel(const int* __restrict__ src,
                            const int* __restrict__ dst) {
    int e = blockIdx.x * blockDim.x + threadIdx.x;
    if (e < N_EDGES) {
        unsigned s = (unsigned)src[e];
        unsigned d = (unsigned)dst[e];
        if (s < N_NODES && d < N_NODES) {
            int pos = atomicAdd(&g_cursor[d], 1);
            g_col[pos] = (int)s;
        }
    }
}

// ---------------- GEMM: C[M,128] = A[M,K] @ W[K,128] (+bias) ----------------
// 64x128 block tile, 128 threads, 8x8 per-thread tile split 4+4 so all
// LDS.128 are phase-conflict-free. K tiled by 16.
template <int K, bool A_SCR, bool C_SCR, bool BIAS>
__global__ void __launch_bounds__(128)
gemm_rt_kernel(const float* __restrict__ A_ext, float* __restrict__ C_ext,
               const float* __restrict__ W, const float* __restrict__ bias) {
    const float* A = A_SCR ? (const float*)g_buf : A_ext;
    float* C = C_SCR ? g_buf : C_ext;

    constexpr int BK = 16;
    __shared__ float As[BK][68];
    __shared__ float Bs[BK][132];

    const int tid = threadIdx.x;
    const int tx = tid & 15;   // col groups at tx*4 and tx*4+64
    const int ty = tid >> 4;   // row groups at ty*4 and ty*4+32
    const int row0 = blockIdx.x * 64;

    float acc[8][8];
#pragma unroll
    for (int i = 0; i < 8; i++)
#pragma unroll
        for (int j = 0; j < 8; j++) acc[i][j] = 0.0f;

    for (int k0 = 0; k0 < K; k0 += BK) {
#pragma unroll
        for (int i = 0; i < 2; i++) {
            const int f4 = i * 128 + tid;      // 0..255
            const int r = f4 >> 2;
            const int q = f4 & 3;
            const int grow = row0 + r;
            float4 v = make_float4(0.f, 0.f, 0.f, 0.f);
            if (grow < N_NODES)
                v = *reinterpret_cast<const float4*>(&A[(size_t)grow * K + k0 + q * 4]);
            As[q * 4 + 0][r] = v.x;
            As[q * 4 + 1][r] = v.y;
            As[q * 4 + 2][r] = v.z;
            As[q * 4 + 3][r] = v.w;
        }
#pragma unroll
        for (int i = 0; i < 4; i++) {
            const int f4 = i * 128 + tid;      // 0..511
            const int kk = f4 >> 5;
            const int c = (f4 & 31) * 4;
            const float4 v = *reinterpret_cast<const float4*>(&W[(size_t)(k0 + kk) * HID + c]);
            Bs[kk][c + 0] = v.x;
            Bs[kk][c + 1] = v.y;
            Bs[kk][c + 2] = v.z;
            Bs[kk][c + 3] = v.w;
        }
        __syncthreads();

#pragma unroll
        for (int kk = 0; kk < BK; kk++) {
            float a[8], b[8];
            *reinterpret_cast<float4*>(&a[0]) = *reinterpret_cast<const float4*>(&As[kk][ty * 4]);
            *reinterpret_cast<float4*>(&a[4]) = *reinterpret_cast<const float4*>(&As[kk][ty * 4 + 32]);
            *reinterpret_cast<float4*>(&b[0]) = *reinterpret_cast<const float4*>(&Bs[kk][tx * 4]);
            *reinterpret_cast<float4*>(&b[4]) = *reinterpret_cast<const float4*>(&Bs[kk][tx * 4 + 64]);
#pragma unroll
            for (int i = 0; i < 8; i++)
#pragma unroll
                for (int j = 0; j < 8; j++)
                    acc[i][j] = fmaf(a[i], b[j], acc[i][j]);
        }
        __syncthreads();
    }

    float bv[8];
#pragma unroll
    for (int j = 0; j < 8; j++)
        bv[j] = BIAS ? bias[tx * 4 + (j & 3) + (j >> 2) * 64] : 0.0f;

#pragma unroll
    for (int i = 0; i < 8; i++) {
        const int grow = row0 + ty * 4 + (i & 3) + (i >> 2) * 32;
        if (grow < N_NODES) {
            float4 v0, v1;
            v0.x = acc[i][0] + bv[0]; v0.y = acc[i][1] + bv[1];
            v0.z = acc[i][2] + bv[2]; v0.w = acc[i][3] + bv[3];
            v1.x = acc[i][4] + bv[4]; v1.y = acc[i][5] + bv[5];
            v1.z = acc[i][6] + bv[6]; v1.w = acc[i][7] + bv[7];
            float* crow = &C[(size_t)grow * HID];
            *reinterpret_cast<float4*>(crow + tx * 4) = v0;
            *reinterpret_cast<float4*>(crow + tx * 4 + 64) = v1;
        }
    }
}

// ---------------- CSR gather aggregation -------------------------------------
// One warp per dst node; lane handles 4 channels as float4.
// o[n] = (RELU ? relu(agg + bias) : agg), agg = dinv[n]^2*h[n] + sum_e norm*h[src]
template <bool H_SCR, bool RELU>
__global__ void __launch_bounds__(256)
gather_kernel(const float* __restrict__ h_ext, float* __restrict__ o_ext,
              const float* __restrict__ bias) {
    const float* h = H_SCR ? (const float*)g_buf : h_ext;
    float* o = H_SCR ? o_ext : g_buf;

    const int n = blockIdx.x * 8 + (threadIdx.x >> 5);
    const int lane = threadIdx.x & 31;
    if (n >= N_NODES) return;

    const float dn = g_dinv[n];
    const int beg = g_rowptr[n];
    const int end = g_rowptr[n + 1];

    float4 acc = reinterpret_cast<const float4*>(h + (size_t)n * HID)[lane];
    const float s2 = dn * dn;
    acc.x *= s2; acc.y *= s2; acc.z *= s2; acc.w *= s2;

    int e = beg;
    for (; e + 2 <= end; e += 2) {
        const int s0 = g_col[e];
        const int s1 = g_col[e + 1];
        const float w0 = dn * g_dinv[s0];
        const float w1 = dn * g_dinv[s1];
        const float4 v0 = reinterpret_cast<const float4*>(h + (size_t)s0 * HID)[lane];
        const float4 v1 = reinterpret_cast<const float4*>(h + (size_t)s1 * HID)[lane];
        acc.x = fmaf(w0, v0.x, acc.x); acc.y = fmaf(w0, v0.y, acc.y);
        acc.z = fmaf(w0, v0.z, acc.z); acc.w = fmaf(w0, v0.w, acc.w);
        acc.x = fmaf(w1, v1.x, acc.x); acc.y = fmaf(w1, v1.y, acc.y);
        acc.z = fmaf(w1, v1.z, acc.z); acc.w = fmaf(w1, v1.w, acc.w);
    }
    if (e < end) {
        const int s0 = g_col[e];
        const float w0 = dn * g_dinv[s0];
        const float4 v0 = reinterpret_cast<const float4*>(h + (size_t)s0 * HID)[lane];
        acc.x = fmaf(w0, v0.x, acc.x); acc.y = fmaf(w0, v0.y, acc.y);
        acc.z = fmaf(w0, v0.z, acc.z); acc.w = fmaf(w0, v0.w, acc.w);
    }

    if (RELU) {
        const float4 b = reinterpret_cast<const float4*>(bias)[lane];
        acc.x = fmaxf(acc.x + b.x, 0.0f);
        acc.y = fmaxf(acc.y + b.y, 0.0f);
        acc.z = fmaxf(acc.z + b.z, 0.0f);
        acc.w = fmaxf(acc.w + b.w, 0.0f);
    }
    reinterpret_cast<float4*>(o + (size_t)n * HID)[lane] = acc;
}

extern "C" void kernel_launch(void* const* d_in, const int* in_sizes, int n_in,
                              void* d_out, int out_size) {
    const float* x   = (const float*)d_in[0];
    const int* ei    = (const int*)d_in[1];   // int64 marshaled as int32
    const float* W1  = (const float*)d_in[2];
    const float* b1  = (const float*)d_in[3];
    const float* W2  = (const float*)d_in[4];
    const float* b2  = (const float*)d_in[5];
    float* out       = (float*)d_out;

    const int* src = ei;            // edge_index[0]
    const int* dst = ei + N_EDGES;  // edge_index[1]

    const int nb = (N_NODES + 255) / 256;
    const int ebk = (N_EDGES + 255) / 256;
    const int gemm_blocks = (N_NODES + 63) / 64;
    const int gather_blocks = (N_NODES + 7) / 8;

    // CSR build + norms
    degi_init_kernel<<<nb, 256>>>();
    degi_count_kernel<<<ebk, 256>>>(dst);
    dinv_kernel<<<nb, 256>>>();
    scan_kernel<<<1, 1024>>>();
    fill_kernel<<<ebk, 256>>>(src, dst);

    // layer 1: h1 = x@W1 (g_buf); h2 = relu(A_hat*h1 + b1) -> out
    gemm_rt_kernel<IN_CH, false, true, false><<<gemm_blocks, 128>>>(x, nullptr, W1, nullptr);
    gather_kernel<true, true><<<gather_blocks, 256>>>(nullptr, out, b1);

    // layer 2 (reassociated): agg2 = A_hat*h2 -> g_buf; out = agg2@W2 + b2
    gather_kernel<false, false><<<gather_blocks, 256>>>(out, nullptr, nullptr);
    gemm_rt_kernel<HID, true, false, true><<<gemm_blocks, 128>>>(nullptr, out, W2, b2);
}

// round 8
// speedup vs baseline: 2.3455x; 1.2887x over previous
#include <cuda_runtime.h>
#include <stdint.h>

#define N_NODES 50000
#define N_EDGES 800000
#define IN_CH 384
#define HID 128

#define SCAN_BLK 256
#define SCAN_NBLK ((N_NODES + SCAN_BLK - 1) / SCAN_BLK)   // 196

// ---------------- scratch (device-code-only references!) ----------------
__device__ __align__(256) float g_buf[N_NODES * HID];  // 25.6MB scratch
__device__ float g_dinv[N_NODES];
__device__ int g_degi[N_NODES];
__device__ int g_rowptr[N_NODES + 1];
__device__ int g_cursor[N_NODES];
__device__ int g_col[N_EDGES];
__device__ int g_bsum[SCAN_NBLK];
__device__ int g_boff[SCAN_NBLK];

// ---------------- degree ----------------
__global__ void degi_init_kernel() {
    int i = blockIdx.x * blockDim.x + threadIdx.x;
    if (i < N_NODES) g_degi[i] = 0;
}

__global__ void degi_count_kernel(const int* __restrict__ dst) {
    int e = blockIdx.x * blockDim.x + threadIdx.x;
    if (e < N_EDGES) {
        unsigned d = (unsigned)dst[e];
        if (d < N_NODES) atomicAdd(&g_degi[d], 1);
    }
}

// ---------------- device-wide exclusive scan (3 phases) ----------------
__global__ void scan_reduce_kernel() {
    __shared__ int sm[SCAN_BLK];
    const int tid = threadIdx.x;
    const int i = blockIdx.x * SCAN_BLK + tid;
    sm[tid] = (i < N_NODES) ? g_degi[i] : 0;
    __syncthreads();
#pragma unroll
    for (int off = SCAN_BLK / 2; off > 0; off >>= 1) {
        if (tid < off) sm[tid] += sm[tid + off];
        __syncthreads();
    }
    if (tid == 0) g_bsum[blockIdx.x] = sm[0];
}

__global__ void scan_bsum_kernel() {
    __shared__ int sm[SCAN_BLK];
    const int tid = threadIdx.x;
    int v = (tid < SCAN_NBLK) ? g_bsum[tid] : 0;
    sm[tid] = v;
    __syncthreads();
#pragma unroll
    for (int off = 1; off < SCAN_BLK; off <<= 1) {
        int t = 0;
        if (tid >= off) t = sm[tid - off];
        __syncthreads();
        if (tid >= off) sm[tid] += t;
        __syncthreads();
    }
    if (tid < SCAN_NBLK) g_boff[tid] = sm[tid] - v;  // exclusive
    if (tid == SCAN_BLK - 1) g_rowptr[N_NODES] = sm[SCAN_BLK - 1];
}

// per-block exclusive scan + base offset; also computes dinv.
__global__ void scan_write_kernel() {
    __shared__ int sm[SCAN_BLK];
    const int tid = threadIdx.x;
    const int i = blockIdx.x * SCAN_BLK + tid;
    const int v = (i < N_NODES) ? g_degi[i] : 0;
    sm[tid] = v;
    __syncthreads();
#pragma unroll
    for (int off = 1; off < SCAN_BLK; off <<= 1) {
        int t = 0;
        if (tid >= off) t = sm[tid - off];
        __syncthreads();
        if (tid >= off) sm[tid] += t;
        __syncthreads();
    }
    if (i < N_NODES) {
        const int pos = g_boff[blockIdx.x] + sm[tid] - v;  // exclusive
        g_rowptr[i] = pos;
        g_cursor[i] = pos;
        g_dinv[i] = rsqrtf(1.0f + (float)v);
    }
}

__global__ void fill_kernel(const int* __restrict__ src,
                            const int* __restrict__ dst) {
    int e = blockIdx.x * blockDim.x + threadIdx.x;
    if (e < N_EDGES) {
        unsigned s = (unsigned)src[e];
        unsigned d = (unsigned)dst[e];
        if (s < N_NODES && d < N_NODES) {
            int pos = atomicAdd(&g_cursor[d], 1);
            g_col[pos] = (int)s;
        }
    }
}

// ---------------- GEMM: C[M,128] = A[M,K] @ W[K,128] (+bias) ----------------
// 64x128 block tile, 128 threads, 8x8 per-thread tile split 4+4 so all
// LDS.128 are phase-conflict-free. K tiled by 16.
template <int K, bool A_SCR, bool C_SCR, bool BIAS>
__global__ void __launch_bounds__(128)
gemm_rt_kernel(const float* __restrict__ A_ext, float* __restrict__ C_ext,
               const float* __restrict__ W, const float* __restrict__ bias) {
    const float* A = A_SCR ? (const float*)g_buf : A_ext;
    float* C = C_SCR ? g_buf : C_ext;

    constexpr int BK = 16;
    __shared__ float As[BK][68];
    __shared__ float Bs[BK][132];

    const int tid = threadIdx.x;
    const int tx = tid & 15;   // col groups at tx*4 and tx*4+64
    const int ty = tid >> 4;   // row groups at ty*4 and ty*4+32
    const int row0 = blockIdx.x * 64;

    float acc[8][8];
#pragma unroll
    for (int i = 0; i < 8; i++)
#pragma unroll
        for (int j = 0; j < 8; j++) acc[i][j] = 0.0f;

    for (int k0 = 0; k0 < K; k0 += BK) {
#pragma unroll
        for (int i = 0; i < 2; i++) {
            const int f4 = i * 128 + tid;      // 0..255
            const int r = f4 >> 2;
            const int q = f4 & 3;
            const int grow = row0 + r;
            float4 v = make_float4(0.f, 0.f, 0.f, 0.f);
            if (grow < N_NODES)
                v = *reinterpret_cast<const float4*>(&A[(size_t)grow * K + k0 + q * 4]);
            As[q * 4 + 0][r] = v.x;
            As[q * 4 + 1][r] = v.y;
            As[q * 4 + 2][r] = v.z;
            As[q * 4 + 3][r] = v.w;
        }
#pragma unroll
        for (int i = 0; i < 4; i++) {
            const int f4 = i * 128 + tid;      // 0..511
            const int kk = f4 >> 5;
            const int c = (f4 & 31) * 4;
            const float4 v = *reinterpret_cast<const float4*>(&W[(size_t)(k0 + kk) * HID + c]);
            Bs[kk][c + 0] = v.x;
            Bs[kk][c + 1] = v.y;
            Bs[kk][c + 2] = v.z;
            Bs[kk][c + 3] = v.w;
        }
        __syncthreads();

#pragma unroll
        for (int kk = 0; kk < BK; kk++) {
            float a[8], b[8];
            *reinterpret_cast<float4*>(&a[0]) = *reinterpret_cast<const float4*>(&As[kk][ty * 4]);
            *reinterpret_cast<float4*>(&a[4]) = *reinterpret_cast<const float4*>(&As[kk][ty * 4 + 32]);
            *reinterpret_cast<float4*>(&b[0]) = *reinterpret_cast<const float4*>(&Bs[kk][tx * 4]);
            *reinterpret_cast<float4*>(&b[4]) = *reinterpret_cast<const float4*>(&Bs[kk][tx * 4 + 64]);
#pragma unroll
            for (int i = 0; i < 8; i++)
#pragma unroll
                for (int j = 0; j < 8; j++)
                    acc[i][j] = fmaf(a[i], b[j], acc[i][j]);
        }
        __syncthreads();
    }

    float bv[8];
#pragma unroll
    for (int j = 0; j < 8; j++)
        bv[j] = BIAS ? bias[tx * 4 + (j & 3) + (j >> 2) * 64] : 0.0f;

#pragma unroll
    for (int i = 0; i < 8; i++) {
        const int grow = row0 + ty * 4 + (i & 3) + (i >> 2) * 32;
        if (grow < N_NODES) {
            float4 v0, v1;
            v0.x = acc[i][0] + bv[0]; v0.y = acc[i][1] + bv[1];
            v0.z = acc[i][2] + bv[2]; v0.w = acc[i][3] + bv[3];
            v1.x = acc[i][4] + bv[4]; v1.y = acc[i][5] + bv[5];
            v1.z = acc[i][6] + bv[6]; v1.w = acc[i][7] + bv[7];
            float* crow = &C[(size_t)grow * HID];
            *reinterpret_cast<float4*>(crow + tx * 4) = v0;
            *reinterpret_cast<float4*>(crow + tx * 4 + 64) = v1;
        }
    }
}

// ---------------- CSR gather aggregation -------------------------------------
// One warp per dst node; lane handles 4 channels as float4.
template <bool H_SCR, bool RELU>
__global__ void __launch_bounds__(256)
gather_kernel(const float* __restrict__ h_ext, float* __restrict__ o_ext,
              const float* __restrict__ bias) {
    const float* h = H_SCR ? (const float*)g_buf : h_ext;
    float* o = H_SCR ? o_ext : g_buf;

    const int n = blockIdx.x * 8 + (threadIdx.x >> 5);
    const int lane = threadIdx.x & 31;
    if (n >= N_NODES) return;

    const float dn = g_dinv[n];
    const int beg = g_rowptr[n];
    const int end = g_rowptr[n + 1];

    float4 acc = reinterpret_cast<const float4*>(h + (size_t)n * HID)[lane];
    const float s2 = dn * dn;
    acc.x *= s2; acc.y *= s2; acc.z *= s2; acc.w *= s2;

    int e = beg;
    for (; e + 2 <= end; e += 2) {
        const int s0 = g_col[e];
        const int s1 = g_col[e + 1];
        const float w0 = dn * g_dinv[s0];
        const float w1 = dn * g_dinv[s1];
        const float4 v0 = reinterpret_cast<const float4*>(h + (size_t)s0 * HID)[lane];
        const float4 v1 = reinterpret_cast<const float4*>(h + (size_t)s1 * HID)[lane];
        acc.x = fmaf(w0, v0.x, acc.x); acc.y = fmaf(w0, v0.y, acc.y);
        acc.z = fmaf(w0, v0.z, acc.z); acc.w = fmaf(w0, v0.w, acc.w);
        acc.x = fmaf(w1, v1.x, acc.x); acc.y = fmaf(w1, v1.y, acc.y);
        acc.z = fmaf(w1, v1.z, acc.z); acc.w = fmaf(w1, v1.w, acc.w);
    }
    if (e < end) {
        const int s0 = g_col[e];
        const float w0 = dn * g_dinv[s0];
        const float4 v0 = reinterpret_cast<const float4*>(h + (size_t)s0 * HID)[lane];
        acc.x = fmaf(w0, v0.x, acc.x); acc.y = fmaf(w0, v0.y, acc.y);
        acc.z = fmaf(w0, v0.z, acc.z); acc.w = fmaf(w0, v0.w, acc.w);
    }

    if (RELU) {
        const float4 b = reinterpret_cast<const float4*>(bias)[lane];
        acc.x = fmaxf(acc.x + b.x, 0.0f);
        acc.y = fmaxf(acc.y + b.y, 0.0f);
        acc.z = fmaxf(acc.z + b.z, 0.0f);
        acc.w = fmaxf(acc.w + b.w, 0.0f);
    }
    reinterpret_cast<float4*>(o + (size_t)n * HID)[lane] = acc;
}

extern "C" void kernel_launch(void* const* d_in, const int* in_sizes, int n_in,
                              void* d_out, int out_size) {
    const float* x   = (const float*)d_in[0];
    const int* ei    = (const int*)d_in[1];   // int64 marshaled as int32
    const float* W1  = (const float*)d_in[2];
    const float* b1  = (const float*)d_in[3];
    const float* W2  = (const float*)d_in[4];
    const float* b2  = (const float*)d_in[5];
    float* out       = (float*)d_out;

    const int* src = ei;            // edge_index[0]
    const int* dst = ei + N_EDGES;  // edge_index[1]

    const int nb = (N_NODES + 255) / 256;
    const int ebk = (N_EDGES + 255) / 256;
    const int gemm_blocks = (N_NODES + 63) / 64;
    const int gather_blocks = (N_NODES + 7) / 8;

    // CSR build + norms (parallel 3-phase scan)
    degi_init_kernel<<<nb, 256>>>();
    degi_count_kernel<<<ebk, 256>>>(dst);
    scan_reduce_kernel<<<SCAN_NBLK, SCAN_BLK>>>();
    scan_bsum_kernel<<<1, SCAN_BLK>>>();
    scan_write_kernel<<<SCAN_NBLK, SCAN_BLK>>>();
    fill_kernel<<<ebk, 256>>>(src, dst);

    // layer 1: h1 = x@W1 (g_buf); h2 = relu(A_hat*h1 + b1) -> out
    gemm_rt_kernel<IN_CH, false, true, false><<<gemm_blocks, 128>>>(x, nullptr, W1, nullptr);
    gather_kernel<true, true><<<gather_blocks, 256>>>(nullptr, out, b1);

    // layer 2 (reassociated): agg2 = A_hat*h2 -> g_buf; out = agg2@W2 + b2
    gather_kernel<false, false><<<gather_blocks, 256>>>(out, nullptr, nullptr);
    gemm_rt_kernel<HID, true, false, true><<<gemm_blocks, 128>>>(nullptr, out, W2, b2);
}

// round 10
// speedup vs baseline: 3.3843x; 1.4429x over previous
#include <cuda_runtime.h>
#include <stdint.h>

#define N_NODES 50000
#define N_EDGES 800000
#define IN_CH 384
#define HID 128

#define SCAN_BLK 256
#define SCAN_NBLK ((N_NODES + SCAN_BLK - 1) / SCAN_BLK)   // 196

// ---------------- scratch (device-code-only references!) ----------------
__device__ __align__(256) float g_buf[N_NODES * HID];  // 25.6MB scratch
__device__ float g_dinv[N_NODES];
__device__ int g_degi[N_NODES];
__device__ int g_rowptr[N_NODES + 1];
__device__ int g_cursor[N_NODES];
__device__ int g_col[N_EDGES];
__device__ int g_bsum[SCAN_NBLK];
__device__ int g_boff[SCAN_NBLK];

// ---------------- degree ----------------
__global__ void degi_init_kernel() {
    int i = blockIdx.x * blockDim.x + threadIdx.x;
    if (i < N_NODES) g_degi[i] = 0;
}

__global__ void degi_count_kernel(const int* __restrict__ dst) {
    int e = blockIdx.x * blockDim.x + threadIdx.x;
    if (e < N_EDGES) {
        unsigned d = (unsigned)dst[e];
        if (d < N_NODES) atomicAdd(&g_degi[d], 1);
    }
}

// ---------------- device-wide exclusive scan (3 phases) ----------------
__global__ void scan_reduce_kernel() {
    __shared__ int sm[SCAN_BLK];
    const int tid = threadIdx.x;
    const int i = blockIdx.x * SCAN_BLK + tid;
    sm[tid] = (i < N_NODES) ? g_degi[i] : 0;
    __syncthreads();
#pragma unroll
    for (int off = SCAN_BLK / 2; off > 0; off >>= 1) {
        if (tid < off) sm[tid] += sm[tid + off];
        __syncthreads();
    }
    if (tid == 0) g_bsum[blockIdx.x] = sm[0];
}

__global__ void scan_bsum_kernel() {
    __shared__ int sm[SCAN_BLK];
    const int tid = threadIdx.x;
    int v = (tid < SCAN_NBLK) ? g_bsum[tid] : 0;
    sm[tid] = v;
    __syncthreads();
#pragma unroll
    for (int off = 1; off < SCAN_BLK; off <<= 1) {
        int t = 0;
        if (tid >= off) t = sm[tid - off];
        __syncthreads();
        if (tid >= off) sm[tid] += t;
        __syncthreads();
    }
    if (tid < SCAN_NBLK) g_boff[tid] = sm[tid] - v;  // exclusive
    if (tid == SCAN_BLK - 1) g_rowptr[N_NODES] = sm[SCAN_BLK - 1];
}

__global__ void scan_write_kernel() {
    __shared__ int sm[SCAN_BLK];
    const int tid = threadIdx.x;
    const int i = blockIdx.x * SCAN_BLK + tid;
    const int v = (i < N_NODES) ? g_degi[i] : 0;
    sm[tid] = v;
    __syncthreads();
#pragma unroll
    for (int off = 1; off < SCAN_BLK; off <<= 1) {
        int t = 0;
        if (tid >= off) t = sm[tid - off];
        __syncthreads();
        if (tid >= off) sm[tid] += t;
        __syncthreads();
    }
    if (i < N_NODES) {
        const int pos = g_boff[blockIdx.x] + sm[tid] - v;
        g_rowptr[i] = pos;
        g_cursor[i] = pos;
        g_dinv[i] = rsqrtf(1.0f + (float)v);
    }
}

__global__ void fill_kernel(const int* __restrict__ src,
                            const int* __restrict__ dst) {
    int e = blockIdx.x * blockDim.x + threadIdx.x;
    if (e < N_EDGES) {
        unsigned s = (unsigned)src[e];
        unsigned d = (unsigned)dst[e];
        if (s < N_NODES && d < N_NODES) {
            int pos = atomicAdd(&g_cursor[d], 1);
            g_col[pos] = (int)s;
        }
    }
}

// ---------------- tf32 mma.sync helpers ----------------
__device__ __forceinline__ uint32_t f2tf32(float x) {
    uint32_t y;
    asm("cvt.rna.tf32.f32 %0, %1;" : "=r"(y) : "f"(x));
    return y;
}

__device__ __forceinline__ void mma16n8k8(float* d, const uint32_t* a,
                                          const uint32_t* b) {
    asm volatile(
        "mma.sync.aligned.m16n8k8.row.col.f32.tf32.tf32.f32 "
        "{%0,%1,%2,%3}, {%4,%5,%6,%7}, {%8,%9}, {%0,%1,%2,%3};"
        : "+f"(d[0]), "+f"(d[1]), "+f"(d[2]), "+f"(d[3])
        : "r"(a[0]), "r"(a[1]), "r"(a[2]), "r"(a[3]), "r"(b[0]), "r"(b[1]));
}

// ---------------- tf32 tensor GEMM: C[M,128] = A[M,K] @ W[K,128] (+bias) ----
// 128 threads, block tile 64x128, warps 2x2 (warp tile 32x64), BK=16.
// A staged tf32 in As[64][20], W staged tf32 in Bs[16][136] (conflict-free).
template <int K, bool A_SCR, bool C_SCR, bool BIAS>
__global__ void __launch_bounds__(128)
gemm_mma_kernel(const float* __restrict__ A_ext, float* __restrict__ C_ext,
                const float* __restrict__ W, const float* __restrict__ bias) {
    const float* A = A_SCR ? (const float*)g_buf : A_ext;
    float* C = C_SCR ? g_buf : C_ext;

    constexpr int BK = 16;
    __shared__ uint32_t As[64][BK + 4];   // stride 20 words
    __shared__ uint32_t Bs[BK][136];      // stride 136 words

    const int tid = threadIdx.x;
    const int wid = tid >> 5;
    const int lane = tid & 31;
    const int g = lane >> 2;    // 0..7
    const int tg = lane & 3;    // 0..3
    const int m_w = (wid & 1) * 32;
    const int n_w = (wid >> 1) * 64;
    const int row0 = blockIdx.x * 64;

    float acc[2][8][4];
#pragma unroll
    for (int mt = 0; mt < 2; mt++)
#pragma unroll
        for (int nt = 0; nt < 8; nt++)
#pragma unroll
            for (int r = 0; r < 4; r++) acc[mt][nt][r] = 0.0f;

    for (int k0 = 0; k0 < K; k0 += BK) {
        // A tile: 64 rows x 16 k = 256 float4, 2 per thread
#pragma unroll
        for (int i = 0; i < 2; i++) {
            const int f4 = i * 128 + tid;
            const int r = f4 >> 2;
            const int q = f4 & 3;
            const int grow = row0 + r;
            float4 v = make_float4(0.f, 0.f, 0.f, 0.f);
            if (grow < N_NODES)
                v = *reinterpret_cast<const float4*>(&A[(size_t)grow * K + k0 + q * 4]);
            As[r][q * 4 + 0] = f2tf32(v.x);
            As[r][q * 4 + 1] = f2tf32(v.y);
            As[r][q * 4 + 2] = f2tf32(v.z);
            As[r][q * 4 + 3] = f2tf32(v.w);
        }
        // B tile: 16 k x 128 n = 512 float4, 4 per thread (W is [K][128])
#pragma unroll
        for (int i = 0; i < 4; i++) {
            const int f4 = i * 128 + tid;
            const int kk = f4 >> 5;
            const int c = (f4 & 31) * 4;
            const float4 v = *reinterpret_cast<const float4*>(&W[(size_t)(k0 + kk) * HID + c]);
            Bs[kk][c + 0] = f2tf32(v.x);
            Bs[kk][c + 1] = f2tf32(v.y);
            Bs[kk][c + 2] = f2tf32(v.z);
            Bs[kk][c + 3] = f2tf32(v.w);
        }
        __syncthreads();

#pragma unroll
        for (int s = 0; s < 2; s++) {
            uint32_t bf[8][2];
#pragma unroll
            for (int nt = 0; nt < 8; nt++) {
                bf[nt][0] = Bs[s * 8 + tg][n_w + nt * 8 + g];
                bf[nt][1] = Bs[s * 8 + tg + 4][n_w + nt * 8 + g];
            }
            uint32_t af[2][4];
#pragma unroll
            for (int mt = 0; mt < 2; mt++) {
                af[mt][0] = As[m_w + mt * 16 + g][s * 8 + tg];
                af[mt][1] = As[m_w + mt * 16 + g + 8][s * 8 + tg];
                af[mt][2] = As[m_w + mt * 16 + g][s * 8 + tg + 4];
                af[mt][3] = As[m_w + mt * 16 + g + 8][s * 8 + tg + 4];
            }
#pragma unroll
            for (int mt = 0; mt < 2; mt++)
#pragma unroll
                for (int nt = 0; nt < 8; nt++)
                    mma16n8k8(acc[mt][nt], af[mt], bf[nt]);
        }
        __syncthreads();
    }

    // epilogue: d0,d1 -> (r0, c0..c0+1); d2,d3 -> (r0+8, c0..c0+1)
#pragma unroll
    for (int mt = 0; mt < 2; mt++) {
        const int r0 = row0 + m_w + mt * 16 + g;
#pragma unroll
        for (int nt = 0; nt < 8; nt++) {
            const int c0 = n_w + nt * 8 + 2 * tg;
            float b0 = 0.f, b1 = 0.f;
            if (BIAS) { b0 = bias[c0]; b1 = bias[c0 + 1]; }
            if (r0 < N_NODES) {
                float2 v = make_float2(acc[mt][nt][0] + b0, acc[mt][nt][1] + b1);
                *reinterpret_cast<float2*>(&C[(size_t)r0 * HID + c0]) = v;
            }
            if (r0 + 8 < N_NODES) {
                float2 v = make_float2(acc[mt][nt][2] + b0, acc[mt][nt][3] + b1);
                *reinterpret_cast<float2*>(&C[(size_t)(r0 + 8) * HID + c0]) = v;
            }
        }
    }
}

// ---------------- CSR gather aggregation -------------------------------------
template <bool H_SCR, bool RELU>
__global__ void __launch_bounds__(256)
gather_kernel(const float* __restrict__ h_ext, float* __restrict__ o_ext,
              const float* __restrict__ bias) {
    const float* h = H_SCR ? (const float*)g_buf : h_ext;
    float* o = H_SCR ? o_ext : g_buf;

    const int n = blockIdx.x * 8 + (threadIdx.x >> 5);
    const int lane = threadIdx.x & 31;
    if (n >= N_NODES) return;

    const float dn = g_dinv[n];
    const int beg = g_rowptr[n];
    const int end = g_rowptr[n + 1];

    float4 acc = reinterpret_cast<const float4*>(h + (size_t)n * HID)[lane];
    const float s2 = dn * dn;
    acc.x *= s2; acc.y *= s2; acc.z *= s2; acc.w *= s2;

    int e = beg;
    for (; e + 2 <= end; e += 2) {
        const int s0 = g_col[e];
        const int s1 = g_col[e + 1];
        const float w0 = dn * g_dinv[s0];
        const float w1 = dn * g_dinv[s1];
        const float4 v0 = reinterpret_cast<const float4*>(h + (size_t)s0 * HID)[lane];
        const float4 v1 = reinterpret_cast<const float4*>(h + (size_t)s1 * HID)[lane];
        acc.x = fmaf(w0, v0.x, acc.x); acc.y = fmaf(w0, v0.y, acc.y);
        acc.z = fmaf(w0, v0.z, acc.z); acc.w = fmaf(w0, v0.w, acc.w);
        acc.x = fmaf(w1, v1.x, acc.x); acc.y = fmaf(w1, v1.y, acc.y);
        acc.z = fmaf(w1, v1.z, acc.z); acc.w = fmaf(w1, v1.w, acc.w);
    }
    if (e < end) {
        const int s0 = g_col[e];
        const float w0 = dn * g_dinv[s0];
        const float4 v0 = reinterpret_cast<const float4*>(h + (size_t)s0 * HID)[lane];
        acc.x = fmaf(w0, v0.x, acc.x); acc.y = fmaf(w0, v0.y, acc.y);
        acc.z = fmaf(w0, v0.z, acc.z); acc.w = fmaf(w0, v0.w, acc.w);
    }

    if (RELU) {
        const float4 b = reinterpret_cast<const float4*>(bias)[lane];
        acc.x = fmaxf(acc.x + b.x, 0.0f);
        acc.y = fmaxf(acc.y + b.y, 0.0f);
        acc.z = fmaxf(acc.z + b.z, 0.0f);
        acc.w = fmaxf(acc.w + b.w, 0.0f);
    }
    reinterpret_cast<float4*>(o + (size_t)n * HID)[lane] = acc;
}

extern "C" void kernel_launch(void* const* d_in, const int* in_sizes, int n_in,
                              void* d_out, int out_size) {
    const float* x   = (const float*)d_in[0];
    const int* ei    = (const int*)d_in[1];   // int64 marshaled as int32
    const float* W1  = (const float*)d_in[2];
    const float* b1  = (const float*)d_in[3];
    const float* W2  = (const float*)d_in[4];
    const float* b2  = (const float*)d_in[5];
    float* out       = (float*)d_out;

    const int* src = ei;            // edge_index[0]
    const int* dst = ei + N_EDGES;  // edge_index[1]

    const int nb = (N_NODES + 255) / 256;
    const int ebk = (N_EDGES + 255) / 256;
    const int gemm_blocks = (N_NODES + 63) / 64;
    const int gather_blocks = (N_NODES + 7) / 8;

    // CSR build + norms
    degi_init_kernel<<<nb, 256>>>();
    degi_count_kernel<<<ebk, 256>>>(dst);
    scan_reduce_kernel<<<SCAN_NBLK, SCAN_BLK>>>();
    scan_bsum_kernel<<<1, SCAN_BLK>>>();
    scan_write_kernel<<<SCAN_NBLK, SCAN_BLK>>>();
    fill_kernel<<<ebk, 256>>>(src, dst);

    // layer 1: h1 = x@W1 (g_buf, tf32 mma); h2 = relu(A_hat*h1 + b1) -> out
    gemm_mma_kernel<IN_CH, false, true, false><<<gemm_blocks, 128>>>(x, nullptr, W1, nullptr);
    gather_kernel<true, true><<<gather_blocks, 256>>>(nullptr, out, b1);

    // layer 2 (reassociated): agg2 = A_hat*h2 -> g_buf; out = agg2@W2 + b2
    gather_kernel<false, false><<<gather_blocks, 256>>>(out, nullptr, nullptr);
    gemm_mma_kernel<HID, true, false, true><<<gemm_blocks, 128>>>(nullptr, out, W2, b2);
}

// round 11
// speedup vs baseline: 3.8054x; 1.1244x over previous
#include <cuda_runtime.h>
#include <stdint.h>

#define N_NODES 50000
#define N_EDGES 800000
#define IN_CH 384
#define HID 128

#define SCAN_BLK 256
#define SCAN_NBLK ((N_NODES + SCAN_BLK - 1) / SCAN_BLK)   // 196

// ---------------- scratch (device-code-only references!) ----------------
__device__ __align__(256) float g_buf[N_NODES * HID];  // 25.6MB scratch
__device__ float g_dinv[N_NODES];
__device__ int g_degi[N_NODES];
__device__ int g_rowptr[N_NODES + 1];
__device__ int g_cursor[N_NODES];
__device__ int g_col[N_EDGES];
__device__ int g_bsum[SCAN_NBLK];

// ---------------- degree ----------------
__global__ void degi_init_kernel() {
    int i = blockIdx.x * blockDim.x + threadIdx.x;
    if (i < N_NODES) g_degi[i] = 0;
}

__global__ void degi_count_kernel(const int* __restrict__ dst) {
    int e = blockIdx.x * blockDim.x + threadIdx.x;
    if (e < N_EDGES) {
        unsigned d = (unsigned)dst[e];
        if (d < N_NODES) atomicAdd(&g_degi[d], 1);
    }
}

// ---------------- device-wide exclusive scan (2 phases) ----------------
__global__ void scan_reduce_kernel() {
    __shared__ int sm[SCAN_BLK];
    const int tid = threadIdx.x;
    const int i = blockIdx.x * SCAN_BLK + tid;
    sm[tid] = (i < N_NODES) ? g_degi[i] : 0;
    __syncthreads();
#pragma unroll
    for (int off = SCAN_BLK / 2; off > 0; off >>= 1) {
        if (tid < off) sm[tid] += sm[tid + off];
        __syncthreads();
    }
    if (tid == 0) g_bsum[blockIdx.x] = sm[0];
}

// fused: per-block it (a) scans all 196 block sums in smem to get its offset,
// (b) scans its own 256-element chunk, (c) emits rowptr/cursor/dinv.
__global__ void scan_write_kernel() {
    __shared__ int sb[SCAN_BLK];
    __shared__ int sm[SCAN_BLK];
    __shared__ int myorig;
    const int tid = threadIdx.x;
    const int bid = blockIdx.x;

    const int bv = (tid < SCAN_NBLK) ? g_bsum[tid] : 0;
    sb[tid] = bv;
    if (tid == bid) myorig = bv;

    const int i = bid * SCAN_BLK + tid;
    const int v = (i < N_NODES) ? g_degi[i] : 0;
    sm[tid] = v;
    __syncthreads();

#pragma unroll
    for (int off = 1; off < SCAN_BLK; off <<= 1) {
        int t1 = 0, t2 = 0;
        if (tid >= off) { t1 = sb[tid - off]; t2 = sm[tid - off]; }
        __syncthreads();
        if (tid >= off) { sb[tid] += t1; sm[tid] += t2; }
        __syncthreads();
    }

    if (bid == 0 && tid == 0) g_rowptr[N_NODES] = sb[SCAN_NBLK - 1];
    const int excl_b = sb[bid] - myorig;
    if (i < N_NODES) {
        const int pos = excl_b + sm[tid] - v;   // exclusive within chunk
        g_rowptr[i] = pos;
        g_cursor[i] = pos;
        g_dinv[i] = rsqrtf(1.0f + (float)v);
    }
}

__global__ void fill_kernel(const int* __restrict__ src,
                            const int* __restrict__ dst) {
    int e = blockIdx.x * blockDim.x + threadIdx.x;
    if (e < N_EDGES) {
        unsigned s = (unsigned)src[e];
        unsigned d = (unsigned)dst[e];
        if (s < N_NODES && d < N_NODES) {
            int pos = atomicAdd(&g_cursor[d], 1);
            g_col[pos] = (int)s;
        }
    }
}

// ---------------- tf32 mma.sync helpers ----------------
__device__ __forceinline__ uint32_t f2tf32(float x) {
    uint32_t y;
    asm("cvt.rna.tf32.f32 %0, %1;" : "=r"(y) : "f"(x));
    return y;
}

__device__ __forceinline__ void mma16n8k8(float* d, const uint32_t* a,
                                          const uint32_t* b) {
    asm volatile(
        "mma.sync.aligned.m16n8k8.row.col.f32.tf32.tf32.f32 "
        "{%0,%1,%2,%3}, {%4,%5,%6,%7}, {%8,%9}, {%0,%1,%2,%3};"
        : "+f"(d[0]), "+f"(d[1]), "+f"(d[2]), "+f"(d[3])
        : "r"(a[0]), "r"(a[1]), "r"(a[2]), "r"(a[3]), "r"(b[0]), "r"(b[1]));
}

// ---------------- tf32 tensor GEMM: C[M,128] = A[M,K] @ W[K,128] (+bias) ----
template <int K, bool A_SCR, bool C_SCR, bool BIAS>
__global__ void __launch_bounds__(128)
gemm_mma_kernel(const float* __restrict__ A_ext, float* __restrict__ C_ext,
                const float* __restrict__ W, const float* __restrict__ bias) {
    const float* A = A_SCR ? (const float*)g_buf : A_ext;
    float* C = C_SCR ? g_buf : C_ext;

    constexpr int BK = 16;
    __shared__ uint32_t As[64][BK + 4];   // stride 20 words
    __shared__ uint32_t Bs[BK][136];      // stride 136 words

    const int tid = threadIdx.x;
    const int wid = tid >> 5;
    const int lane = tid & 31;
    const int g = lane >> 2;    // 0..7
    const int tg = lane & 3;    // 0..3
    const int m_w = (wid & 1) * 32;
    const int n_w = (wid >> 1) * 64;
    const int row0 = blockIdx.x * 64;

    float acc[2][8][4];
#pragma unroll
    for (int mt = 0; mt < 2; mt++)
#pragma unroll
        for (int nt = 0; nt < 8; nt++)
#pragma unroll
            for (int r = 0; r < 4; r++) acc[mt][nt][r] = 0.0f;

    for (int k0 = 0; k0 < K; k0 += BK) {
#pragma unroll
        for (int i = 0; i < 2; i++) {
            const int f4 = i * 128 + tid;
            const int r = f4 >> 2;
            const int q = f4 & 3;
            const int grow = row0 + r;
            float4 v = make_float4(0.f, 0.f, 0.f, 0.f);
            if (grow < N_NODES)
                v = *reinterpret_cast<const float4*>(&A[(size_t)grow * K + k0 + q * 4]);
            As[r][q * 4 + 0] = f2tf32(v.x);
            As[r][q * 4 + 1] = f2tf32(v.y);
            As[r][q * 4 + 2] = f2tf32(v.z);
            As[r][q * 4 + 3] = f2tf32(v.w);
        }
#pragma unroll
        for (int i = 0; i < 4; i++) {
            const int f4 = i * 128 + tid;
            const int kk = f4 >> 5;
            const int c = (f4 & 31) * 4;
            const float4 v = *reinterpret_cast<const float4*>(&W[(size_t)(k0 + kk) * HID + c]);
            Bs[kk][c + 0] = f2tf32(v.x);
            Bs[kk][c + 1] = f2tf32(v.y);
            Bs[kk][c + 2] = f2tf32(v.z);
            Bs[kk][c + 3] = f2tf32(v.w);
        }
        __syncthreads();

#pragma unroll
        for (int s = 0; s < 2; s++) {
            uint32_t bf[8][2];
#pragma unroll
            for (int nt = 0; nt < 8; nt++) {
                bf[nt][0] = Bs[s * 8 + tg][n_w + nt * 8 + g];
                bf[nt][1] = Bs[s * 8 + tg + 4][n_w + nt * 8 + g];
            }
            uint32_t af[2][4];
#pragma unroll
            for (int mt = 0; mt < 2; mt++) {
                af[mt][0] = As[m_w + mt * 16 + g][s * 8 + tg];
                af[mt][1] = As[m_w + mt * 16 + g + 8][s * 8 + tg];
                af[mt][2] = As[m_w + mt * 16 + g][s * 8 + tg + 4];
                af[mt][3] = As[m_w + mt * 16 + g + 8][s * 8 + tg + 4];
            }
#pragma unroll
            for (int mt = 0; mt < 2; mt++)
#pragma unroll
                for (int nt = 0; nt < 8; nt++)
                    mma16n8k8(acc[mt][nt], af[mt], bf[nt]);
        }
        __syncthreads();
    }

#pragma unroll
    for (int mt = 0; mt < 2; mt++) {
        const int r0 = row0 + m_w + mt * 16 + g;
#pragma unroll
        for (int nt = 0; nt < 8; nt++) {
            const int c0 = n_w + nt * 8 + 2 * tg;
            float b0 = 0.f, b1 = 0.f;
            if (BIAS) { b0 = bias[c0]; b1 = bias[c0 + 1]; }
            if (r0 < N_NODES) {
                float2 v = make_float2(acc[mt][nt][0] + b0, acc[mt][nt][1] + b1);
                *reinterpret_cast<float2*>(&C[(size_t)r0 * HID + c0]) = v;
            }
            if (r0 + 8 < N_NODES) {
                float2 v = make_float2(acc[mt][nt][2] + b0, acc[mt][nt][3] + b1);
                *reinterpret_cast<float2*>(&C[(size_t)(r0 + 8) * HID + c0]) = v;
            }
        }
    }
}

// ---------------- CSR gather aggregation (4-edge unroll) ---------------------
template <bool H_SCR, bool RELU>
__global__ void __launch_bounds__(256)
gather_kernel(const float* __restrict__ h_ext, float* __restrict__ o_ext,
              const float* __restrict__ bias) {
    const float* h = H_SCR ? (const float*)g_buf : h_ext;
    float* o = H_SCR ? o_ext : g_buf;

    const int n = blockIdx.x * 8 + (threadIdx.x >> 5);
    const int lane = threadIdx.x & 31;
    if (n >= N_NODES) return;

    const float dn = g_dinv[n];
    const int beg = g_rowptr[n];
    const int end = g_rowptr[n + 1];

    float4 acc = reinterpret_cast<const float4*>(h + (size_t)n * HID)[lane];
    const float s2 = dn * dn;
    acc.x *= s2; acc.y *= s2; acc.z *= s2; acc.w *= s2;

    int e = beg;
    for (; e + 4 <= end; e += 4) {
        const int s0 = g_col[e];
        const int s1 = g_col[e + 1];
        const int s2i = g_col[e + 2];
        const int s3 = g_col[e + 3];
        const float w0 = dn * g_dinv[s0];
        const float w1 = dn * g_dinv[s1];
        const float w2 = dn * g_dinv[s2i];
        const float w3 = dn * g_dinv[s3];
        const float4 v0 = reinterpret_cast<const float4*>(h + (size_t)s0 * HID)[lane];
        const float4 v1 = reinterpret_cast<const float4*>(h + (size_t)s1 * HID)[lane];
        const float4 v2 = reinterpret_cast<const float4*>(h + (size_t)s2i * HID)[lane];
        const float4 v3 = reinterpret_cast<const float4*>(h + (size_t)s3 * HID)[lane];
        acc.x = fmaf(w0, v0.x, acc.x); acc.y = fmaf(w0, v0.y, acc.y);
        acc.z = fmaf(w0, v0.z, acc.z); acc.w = fmaf(w0, v0.w, acc.w);
        acc.x = fmaf(w1, v1.x, acc.x); acc.y = fmaf(w1, v1.y, acc.y);
        acc.z = fmaf(w1, v1.z, acc.z); acc.w = fmaf(w1, v1.w, acc.w);
        acc.x = fmaf(w2, v2.x, acc.x); acc.y = fmaf(w2, v2.y, acc.y);
        acc.z = fmaf(w2, v2.z, acc.z); acc.w = fmaf(w2, v2.w, acc.w);
        acc.x = fmaf(w3, v3.x, acc.x); acc.y = fmaf(w3, v3.y, acc.y);
        acc.z = fmaf(w3, v3.z, acc.z); acc.w = fmaf(w3, v3.w, acc.w);
    }
    for (; e < end; e++) {
        const int s0 = g_col[e];
        const float w0 = dn * g_dinv[s0];
        const float4 v0 = reinterpret_cast<const float4*>(h + (size_t)s0 * HID)[lane];
        acc.x = fmaf(w0, v0.x, acc.x); acc.y = fmaf(w0, v0.y, acc.y);
        acc.z = fmaf(w0, v0.z, acc.z); acc.w = fmaf(w0, v0.w, acc.w);
    }

    if (RELU) {
        const float4 b = reinterpret_cast<const float4*>(bias)[lane];
        acc.x = fmaxf(acc.x + b.x, 0.0f);
        acc.y = fmaxf(acc.y + b.y, 0.0f);
        acc.z = fmaxf(acc.z + b.z, 0.0f);
        acc.w = fmaxf(acc.w + b.w, 0.0f);
    }
    reinterpret_cast<float4*>(o + (size_t)n * HID)[lane] = acc;
}

extern "C" void kernel_launch(void* const* d_in, const int* in_sizes, int n_in,
                              void* d_out, int out_size) {
    const float* x   = (const float*)d_in[0];
    const int* ei    = (const int*)d_in[1];   // int64 marshaled as int32
    const float* W1  = (const float*)d_in[2];
    const float* b1  = (const float*)d_in[3];
    const float* W2  = (const float*)d_in[4];
    const float* b2  = (const float*)d_in[5];
    float* out       = (float*)d_out;

    const int* src = ei;            // edge_index[0]
    const int* dst = ei + N_EDGES;  // edge_index[1]

    const int nb = (N_NODES + 255) / 256;
    const int ebk = (N_EDGES + 255) / 256;
    const int gemm_blocks = (N_NODES + 63) / 64;
    const int gather_blocks = (N_NODES + 7) / 8;

    // fork: CSR build on side stream, GEMM1 on the main (legacy) stream
    cudaStream_t s1;
    cudaStreamCreateWithFlags(&s1, cudaStreamNonBlocking);
    cudaEvent_t ev_fork, ev_join;
    cudaEventCreateWithFlags(&ev_fork, cudaEventDisableTiming);
    cudaEventCreateWithFlags(&ev_join, cudaEventDisableTiming);

    cudaEventRecord(ev_fork, 0);
    cudaStreamWaitEvent(s1, ev_fork, 0);

    // CSR branch (s1)
    degi_init_kernel<<<nb, 256, 0, s1>>>();
    degi_count_kernel<<<ebk, 256, 0, s1>>>(dst);
    scan_reduce_kernel<<<SCAN_NBLK, SCAN_BLK, 0, s1>>>();
    scan_write_kernel<<<SCAN_NBLK, SCAN_BLK, 0, s1>>>();
    fill_kernel<<<ebk, 256, 0, s1>>>(src, dst);
    cudaEventRecord(ev_join, s1);

    // GEMM1 branch (legacy stream, concurrent): h1 = x@W1 -> g_buf
    gemm_mma_kernel<IN_CH, false, true, false><<<gemm_blocks, 128>>>(x, nullptr, W1, nullptr);

    // join
    cudaStreamWaitEvent(0, ev_join, 0);

    // h2 = relu(A_hat*h1 + b1) -> out
    gather_kernel<true, true><<<gather_blocks, 256>>>(nullptr, out, b1);
    // layer 2 (reassociated): agg2 = A_hat*h2 -> g_buf; out = agg2@W2 + b2
    gather_kernel<false, false><<<gather_blocks, 256>>>(out, nullptr, nullptr);
    gemm_mma_kernel<HID, true, false, true><<<gemm_blocks, 128>>>(nullptr, out, W2, b2);
}